// round 4
// baseline (speedup 1.0000x reference)
#include <cuda_runtime.h>

typedef unsigned int u32;
typedef unsigned long long u64;

static constexpr int Bn  = 4;
static constexpr int Sn  = 4000;
static constexpr int Din = 1024;
static constexpr int Da  = 512;
static constexpr int Ln  = 8921;
static constexpr int M2  = 2 * Ln;       // 17842 rows: [U; V]
static constexpr int M2pad = 17920;      // 140 * 128
static constexpr int Spad  = 4096;       // padded seq per batch for GEMM2 B

// ---- scratch (device globals; no allocation allowed) ----
__device__ float g_xr [(u64)Bn * Sn * Din];       // x rounded to tf32 (row-major)
__device__ float g_wr [(u64)Da * Din];            // W_w rounded (row-major)
__device__ float g_uv2[(u64)M2pad * Da];          // [U; V] tf32, fragment-permuted rows
__device__ float g_z2 [(u64)Bn * Spad * Da];      // z tf32, fragment-permuted rows, padded
__device__ float g_w  [(u64)Bn * Ln * Sn];        // w = V z^T (571 MB)

// single dynamic-shared declaration shared by all kernels
extern __shared__ __align__(1024) char dyn_smem[];

// ---- helpers ----
__device__ __forceinline__ u32 f2tf(float f) {
    u32 u;
    asm("cvt.rna.tf32.f32 %0, %1;" : "=r"(u) : "f"(f));
    return u;
}

__device__ __forceinline__ void cp16(u32 saddr, const void* g) {
    asm volatile("cp.async.cg.shared.global [%0], [%1], 16;\n" :: "r"(saddr), "l"(g));
}

__device__ __forceinline__ void mma8(float* c, u32 a0, u32 a1, u32 a2, u32 a3,
                                     u32 b0, u32 b1) {
    asm volatile(
        "mma.sync.aligned.m16n8k8.row.col.f32.tf32.tf32.f32 "
        "{%0,%1,%2,%3}, {%4,%5,%6,%7}, {%8,%9}, {%0,%1,%2,%3};\n"
        : "+f"(c[0]), "+f"(c[1]), "+f"(c[2]), "+f"(c[3])
        : "r"(a0), "r"(a1), "r"(a2), "r"(a3), "r"(b0), "r"(b1));
}

#define LDS128(v, addr) \
    asm volatile("ld.shared.v4.b32 {%0,%1,%2,%3}, [%4];" \
        : "=r"((v)[0]), "=r"((v)[1]), "=r"((v)[2]), "=r"((v)[3]) : "r"(addr))

// ---- input rounding ----
// sel 0/1: row-major copy+round (x, W). sel 2/3: fragment-permuted rows (U, V).
__global__ void round_k(const float* __restrict__ in, int n4, int sel) {
    int i = blockIdx.x * blockDim.x + threadIdx.x;
    if (i >= n4) return;
    float4 v = ((const float4*)in)[i];
    u32 rx = f2tf(v.x), ry = f2tf(v.y), rz = f2tf(v.z), rw = f2tf(v.w);
    if (sel <= 1) {
        float* out = (sel == 0) ? g_xr : g_wr;
        uint4 o; o.x = rx; o.y = ry; o.z = rz; o.w = rw;
        ((uint4*)out)[i] = o;
    } else {
        float* out = (sel == 2) ? g_uv2 : (g_uv2 + (u64)Ln * Da);
        const int f = i * 4;                 // k multiple of 4
        const int row = f >> 9;              // /512
        const int k   = f & 511;
        u32* base = (u32*)(out + (u64)row * Da + (k >> 2));
        base[0]   = rx;  base[128] = ry;  base[256] = rz;  base[384] = rw;
    }
}

// ---- GEMM1 (mma.sync): z = tanh(x W^T + b) -> g_z2 (permuted, padded) ----
static constexpr int BM = 128, BN = 128, BK = 32, KS = 36;
static constexpr int TILEF = BM * KS;
static constexpr u32 SMEM1_BYTES = 4u * TILEF * 4u;

__global__ void __launch_bounds__(256, 2)
gemm1_k(const float* __restrict__ bias) {
    constexpr int K   = Din;
    constexpr int KIT = K / BK;

    float* smem = (float*)dyn_smem;
    float* As = smem;
    float* Bs = smem + 2 * TILEF;

    const int tid   = threadIdx.x;
    const int nbase = blockIdx.x * BN;
    const int mbase = blockIdx.y * BM;

    const int lr = tid >> 3;
    const int lc = (tid & 7) * 4;
    const float* aG = g_xr + (u64)(mbase + lr) * K + lc;
    const float* bG = g_wr + (u64)(nbase + lr) * K + lc;

    u32 sA = (u32)__cvta_generic_to_shared(As + lr * KS + lc);
    u32 sB = (u32)__cvta_generic_to_shared(Bs + lr * KS + lc);
    const u32 bufB = (u32)TILEF * 4u;

    auto issue = [&](int kt, int buf) {
        const float* a = aG + kt * BK;
        const float* b = bG + kt * BK;
#pragma unroll
        for (int i = 0; i < 4; i++) cp16(sA + buf * bufB + i * (32 * KS * 4), a + (u64)i * 32 * K);
#pragma unroll
        for (int i = 0; i < 4; i++) cp16(sB + buf * bufB + i * (32 * KS * 4), b + (u64)i * 32 * K);
    };

    issue(0, 0); asm volatile("cp.async.commit_group;\n");
    issue(1, 1); asm volatile("cp.async.commit_group;\n");

    const int warp = tid >> 5, lane = tid & 31;
    const int g = lane >> 2, tg = lane & 3;
    const int wm = warp & 3, wn = warp >> 2;

    float c[2][8][4];
#pragma unroll
    for (int mf = 0; mf < 2; mf++)
#pragma unroll
        for (int nf = 0; nf < 8; nf++)
#pragma unroll
            for (int i = 0; i < 4; i++) c[mf][nf][i] = 0.f;

    for (int kt = 0; kt < KIT; kt++) {
        if (kt == KIT - 1) asm volatile("cp.async.wait_group 0;\n");
        else               asm volatile("cp.async.wait_group 1;\n");
        __syncthreads();

        const float* as = As + (kt & 1) * TILEF + (wm * 32) * KS;
        const float* bs = Bs + (kt & 1) * TILEF + (wn * 64) * KS;
#pragma unroll
        for (int ks = 0; ks < 4; ks++) {
            const int k0 = ks * 8;
            u32 a[2][4];
#pragma unroll
            for (int mf = 0; mf < 2; mf++) {
                const float* ar = as + (mf * 16) * KS;
                a[mf][0] = __float_as_uint(ar[(g    ) * KS + k0 + tg    ]);
                a[mf][1] = __float_as_uint(ar[(g + 8) * KS + k0 + tg    ]);
                a[mf][2] = __float_as_uint(ar[(g    ) * KS + k0 + tg + 4]);
                a[mf][3] = __float_as_uint(ar[(g + 8) * KS + k0 + tg + 4]);
            }
#pragma unroll
            for (int nf = 0; nf < 8; nf++) {
                u32 b0 = __float_as_uint(bs[(nf * 8 + g) * KS + k0 + tg    ]);
                u32 b1 = __float_as_uint(bs[(nf * 8 + g) * KS + k0 + tg + 4]);
                mma8(c[0][nf], a[0][0], a[0][1], a[0][2], a[0][3], b0, b1);
                mma8(c[1][nf], a[1][0], a[1][1], a[1][2], a[1][3], b0, b1);
            }
        }
        __syncthreads();
        if (kt + 2 < KIT) { issue(kt + 2, kt & 1); asm volatile("cp.async.commit_group;\n"); }
    }

    // epilogue: tanh(+bias), tf32 round, store permuted+padded into g_z2
#pragma unroll
    for (int mf = 0; mf < 2; mf++) {
#pragma unroll
        for (int nf = 0; nf < 8; nf++) {
            const int r  = mbase + wm * 32 + mf * 16 + g;   // 0..15999
            const int cl = nbase + wn * 64 + nf * 8 + 2 * tg;
            float* cc = c[mf][nf];
            const float b0 = bias[cl], b1 = bias[cl + 1];
            const int c0 = cl & 3, j = cl >> 2;
#pragma unroll
            for (int rr = 0; rr < 2; rr++) {
                const int row = r + rr * 8;
                const int b   = row / Sn;
                const int s   = row - b * Sn;
                u32* dst = (u32*)(g_z2 + ((u64)b * Spad + s) * Da + j);
                dst[c0 * 128]       = f2tf(tanhf(cc[rr * 2 + 0] + b0));
                dst[(c0 + 1) * 128] = f2tf(tanhf(cc[rr * 2 + 1] + b1));
            }
        }
    }
}

// ---- GEMM2 (mma.sync, fragment-permuted layout): [scores; w] = [U; V] @ z^T ----
static constexpr int G2_BM = 128, G2_BN = 256;
static constexpr int G2_STAGES = 3;
static constexpr int G2_KIT = Da / 32;                    // 16
static constexpr u32 G2_AB  = (u32)G2_BM * 128u;          // 16384
static constexpr u32 G2_ST  = G2_AB + (u32)G2_BN * 128u;  // 49152
static constexpr u32 G2_SMEM = G2_ST * G2_STAGES;         // 147456

__global__ void __launch_bounds__(256, 1)
gemm2_k(float* __restrict__ dout) {
    const u32 sb = (u32)__cvta_generic_to_shared(dyn_smem);
    const int tid  = threadIdx.x;
    const int warp = tid >> 5, lane = tid & 31;
    const int g = lane >> 2, tg = lane & 3;
    const int wm = warp & 1, wn = warp >> 1;   // 2(M) x 4(N)
    const int nbase = blockIdx.x * G2_BN;
    const int mbase = blockIdx.y * G2_BM;
    const int bz    = blockIdx.z;

    // cp.async granule assignment: A 4/thread, B 8/thread (16B each)
    const float* Bg = g_z2 + (u64)bz * Spad * Da;
    u32 adst[4]; const float* asrc[4];
#pragma unroll
    for (int i = 0; i < 4; i++) {
        const int gi = tid + i * 256;            // 0..1023
        const int r = gi >> 3, s = gi & 7;
        adst[i] = (u32)(r * 128 + ((s ^ (r & 7)) << 4));
        asrc[i] = g_uv2 + (u64)(mbase + r) * Da + (s >> 1) * 128 + (s & 1) * 4;
    }
    u32 bdst[8]; const float* bsrc[8];
#pragma unroll
    for (int i = 0; i < 8; i++) {
        const int gi = tid + i * 256;            // 0..2047
        const int r = gi >> 3, s = gi & 7;
        bdst[i] = G2_AB + (u32)(r * 128 + ((s ^ (r & 7)) << 4));
        bsrc[i] = Bg + (u64)(nbase + r) * Da + (s >> 1) * 128 + (s & 1) * 4;
    }

    auto load = [&](int kt, int st) {
        const u32 base = sb + (u32)st * G2_ST;
        const int ko = kt * 8;
#pragma unroll
        for (int i = 0; i < 4; i++) cp16(base + adst[i], asrc[i] + ko);
#pragma unroll
        for (int i = 0; i < 8; i++) cp16(base + bdst[i], bsrc[i] + ko);
        asm volatile("cp.async.commit_group;\n");
    };

    load(0, 0); load(1, 1); load(2, 2);

    float acc[4][8][4];
#pragma unroll
    for (int mf = 0; mf < 4; mf++)
#pragma unroll
        for (int nf = 0; nf < 8; nf++)
#pragma unroll
            for (int i = 0; i < 4; i++) acc[mf][nf][i] = 0.f;

    for (int kt = 0; kt < G2_KIT; kt++) {
        const int st = kt % G2_STAGES;
        if      (kt <  G2_KIT - 2) asm volatile("cp.async.wait_group 2;\n");
        else if (kt == G2_KIT - 2) asm volatile("cp.async.wait_group 1;\n");
        else                       asm volatile("cp.async.wait_group 0;\n");
        __syncthreads();

        const u32 stb = sb + (u32)st * G2_ST;
#pragma unroll
        for (int h = 0; h < 2; h++) {
            const u32 sw = (u32)(((2 * tg + h) ^ g) << 4);
            const u32 baseA = stb + (u32)((wm * 64 + g) * 128) + sw;
            const u32 baseB = stb + G2_AB + (u32)((wn * 64 + g) * 128) + sw;

            u32 a[8][4];
#pragma unroll
            for (int mf = 0; mf < 4; mf++) {
                LDS128(a[mf * 2 + 0], baseA + (u32)((mf * 16    ) * 128));
                LDS128(a[mf * 2 + 1], baseA + (u32)((mf * 16 + 8) * 128));
            }
            u32 b[8][4];
#pragma unroll
            for (int nf = 0; nf < 8; nf++)
                LDS128(b[nf], baseB + (u32)(nf * 8 * 128));

#pragma unroll
            for (int ksh = 0; ksh < 2; ksh++) {
#pragma unroll
                for (int mf = 0; mf < 4; mf++)
#pragma unroll
                    for (int nf = 0; nf < 8; nf++)
                        mma8(acc[mf][nf],
                             a[2 * mf][2 * ksh], a[2 * mf + 1][2 * ksh],
                             a[2 * mf][2 * ksh + 1], a[2 * mf + 1][2 * ksh + 1],
                             b[nf][2 * ksh], b[nf][2 * ksh + 1]);
            }
        }
        __syncthreads();
        if (kt + G2_STAGES < G2_KIT) load(kt + G2_STAGES, st);
    }

    // epilogue: rows < Ln -> scores (alpha region of d_out), rows >= Ln -> g_w
#pragma unroll
    for (int mf = 0; mf < 4; mf++) {
#pragma unroll
        for (int nf = 0; nf < 8; nf++) {
            const int cl = nbase + wn * 64 + nf * 8 + 2 * tg;
            if (cl >= Sn) continue;
            const float* cc = acc[mf][nf];
#pragma unroll
            for (int rr = 0; rr < 2; rr++) {
                const int row = mbase + wm * 64 + mf * 16 + rr * 8 + g;
                if (row < M2) {
                    float* dst = (row < Ln)
                        ? (dout + ((u64)bz * Ln + row) * Sn + cl)
                        : (g_w  + ((u64)bz * Ln + (row - Ln)) * Sn + cl);
                    *(float2*)dst = make_float2(cc[rr * 2 + 0], cc[rr * 2 + 1]);
                }
            }
        }
    }
}

// ---- block reduction (256 threads, 8 warps) ----
__device__ __forceinline__ float bred(float v, float* red, bool sum) {
#pragma unroll
    for (int o = 16; o; o >>= 1) {
        float t = __shfl_xor_sync(0xffffffffu, v, o);
        v = sum ? (v + t) : fmaxf(v, t);
    }
    __syncthreads();
    if ((threadIdx.x & 31) == 0) red[threadIdx.x >> 5] = v;
    __syncthreads();
    float out = red[0];
#pragma unroll
    for (int i = 1; i < 8; i++) out = sum ? (out + red[i]) : fmaxf(out, red[i]);
    return out;
}

// ---- finalize: softmax per (b,l) row in place + y ----
__global__ void __launch_bounds__(256)
finalize_k(float* __restrict__ dout, const float* __restrict__ Vb) {
    const int bid = blockIdx.x;
    const int b = bid / Ln;
    const int l = bid - b * Ln;
    float*       arow = dout + (u64)Bn * Ln + ((u64)b * Ln + l) * Sn;
    const float* wrow = g_w  + ((u64)b * Ln + l) * Sn;
    const int tid = threadIdx.x;
    __shared__ float red[8];

    const int base = tid * 4;
    float4 r[4];
    float mx = -3.402823466e38f;
#pragma unroll
    for (int j = 0; j < 4; j++) {
        const int i = base + j * 1024;
        if (i < Sn) {
            r[j] = *(const float4*)(arow + i);
            mx = fmaxf(mx, fmaxf(fmaxf(r[j].x, r[j].y), fmaxf(r[j].z, r[j].w)));
        }
    }
    mx = bred(mx, red, false);

    float s = 0.f;
#pragma unroll
    for (int j = 0; j < 4; j++) {
        const int i = base + j * 1024;
        if (i < Sn) {
            r[j].x = __expf(r[j].x - mx);
            r[j].y = __expf(r[j].y - mx);
            r[j].z = __expf(r[j].z - mx);
            r[j].w = __expf(r[j].w - mx);
            s += r[j].x + r[j].y + r[j].z + r[j].w;
        }
    }
    s = bred(s, red, true);
    const float inv = 1.f / s;

    float y = 0.f;
#pragma unroll
    for (int j = 0; j < 4; j++) {
        const int i = base + j * 1024;
        if (i < Sn) {
            float4 w4 = *(const float4*)(wrow + i);
            float4 a4;
            a4.x = r[j].x * inv; a4.y = r[j].y * inv;
            a4.z = r[j].z * inv; a4.w = r[j].w * inv;
            *(float4*)(arow + i) = a4;
            y += a4.x * w4.x + a4.y * w4.y + a4.z * w4.z + a4.w * w4.w;
        }
    }
    y = bred(y, red, true);
    if (tid == 0) dout[(u64)b * Ln + l] = y + Vb[l];
}

// ---- launch ----
extern "C" void kernel_launch(void* const* d_in, const int* in_sizes, int n_in,
                              void* d_out, int out_size) {
    const float* x  = (const float*)d_in[0];
    const float* Ww = (const float*)d_in[1];
    const float* Wb = (const float*)d_in[2];
    const float* Uw = (const float*)d_in[3];
    const float* Vw = (const float*)d_in[4];
    const float* Vb = (const float*)d_in[5];
    float* out = (float*)d_out;

    cudaFuncSetAttribute(gemm1_k, cudaFuncAttributeMaxDynamicSharedMemorySize, (int)SMEM1_BYTES);
    cudaFuncSetAttribute(gemm2_k, cudaFuncAttributeMaxDynamicSharedMemorySize, (int)G2_SMEM);

    // round inputs to tf32 (float4 element counts)
    round_k<<<(4096000 + 255) / 256, 256>>>(x,  4096000, 0);
    round_k<<<( 131072 + 255) / 256, 256>>>(Ww,  131072, 1);
    round_k<<<(1141888 + 255) / 256, 256>>>(Uw, 1141888, 2);
    round_k<<<(1141888 + 255) / 256, 256>>>(Vw, 1141888, 3);

    // z = tanh(x W^T + b) -> permuted/padded g_z2
    gemm1_k<<<dim3(4, 125, 1), 256, SMEM1_BYTES>>>(Wb);
    // [scores; w] = [U; V] z^T (scores -> alpha region, w -> g_w)
    gemm2_k<<<dim3(16, 140, 4), 256, G2_SMEM>>>(out + (u64)Bn * Ln);
    // softmax rows in place + y
    finalize_k<<<Bn * Ln, 256>>>(out, Vb);
}